// round 14
// baseline (speedup 1.0000x reference)
#include <cuda_runtime.h>
#include <cuda_fp16.h>
#include <cstdint>

// Problem constants
#define S_LEN 2048
#define BATCH 16
#define HID   1024
#define NCH   (BATCH*HID)        // 16384 channels
#define MTOT  (S_LEN*BATCH)      // 32768
#define KTOT  HID                // 1024
#define NTOT  (3*HID)            // 3072

// Scan chunking
#define NC 128
#define CS (S_LEN/NC)            // 16
#define NGRP 64                  // channel groups of 256
#define NBLK (NC*NGRP)           // 8192 scan blocks

// fp16 mma GEMM tiling
#define BM 128
#define BN 128
#define BKH 64
#define STAGES 3
#define A_BYTES (BM*128)         // 16 KB
#define STG_BYTES (2*A_BYTES)    // 32 KB
#define SMEM_BYTES (STAGES*STG_BYTES)   // 96 KB
#define KTILES (KTOT/BKH)        // 16

#define SCAN_SMEM (3*CS*256*4)   // 48 KB

// Scratch (device globals only)
__device__ __half g_Yh[(size_t)MTOT*NTOT];    // 201 MB : pre-activations (fp16)
__device__ __half g_Xh[(size_t)MTOT*HID];     // 67 MB  : layer input (fp16)
__device__ __half g_Wh[(size_t)NTOT*KTOT];    // 6 MB   : current-layer W (fp16)
__device__ float2 g_AB[(size_t)NBLK*256];     // 16 MB  : chunk aggregates
__device__ float  g_incl[(size_t)NBLK*256];   // 8 MB   : chunk inclusive values
__device__ int    g_flag[NBLK];               // look-back flags

// ---------------------------------------------------------------------------
__device__ __forceinline__ void cp16(uint32_t smem, const void* gmem) {
    asm volatile("cp.async.cg.shared.global [%0], [%1], 16;\n" :: "r"(smem), "l"(gmem));
}
__device__ __forceinline__ void cp_commit() {
    asm volatile("cp.async.commit_group;\n" ::: "memory");
}

__device__ __forceinline__ void ldsm4(uint32_t* r, uint32_t addr) {
    asm volatile("ldmatrix.sync.aligned.m8n8.x4.shared.b16 {%0,%1,%2,%3}, [%4];"
                 : "=r"(r[0]), "=r"(r[1]), "=r"(r[2]), "=r"(r[3]) : "r"(addr));
}

__device__ __forceinline__ void mma_f16(float c[4], const uint32_t a[4], const uint32_t b[2]) {
    asm volatile(
        "mma.sync.aligned.m16n8k16.row.col.f32.f16.f16.f32 "
        "{%0,%1,%2,%3}, {%4,%5,%6,%7}, {%8,%9}, {%0,%1,%2,%3};\n"
        : "+f"(c[0]), "+f"(c[1]), "+f"(c[2]), "+f"(c[3])
        : "r"(a[0]), "r"(a[1]), "r"(a[2]), "r"(a[3]), "r"(b[0]), "r"(b[1]));
}

__device__ __forceinline__ float sigmoidf_(float v) { return 1.f / (1.f + __expf(-v)); }
__device__ __forceinline__ float tanhf_(float v)    { return 2.f / (1.f + __expf(-2.f * v)) - 1.f; }

// ---------------------------------------------------------------------------
__global__ void qrnn_embed(const int* __restrict__ x, const float* __restrict__ emb) {
    int tid = blockIdx.x * blockDim.x + threadIdx.x;
    int m  = tid >> 7;
    int hv = tid & 127;
    int tok = x[m];
    const float4* src = reinterpret_cast<const float4*>(emb) + (size_t)tok * 256 + hv * 2;
    float4 f0 = src[0], f1 = src[1];
    __half2 h[4];
    h[0] = __floats2half2_rn(f0.x, f0.y);
    h[1] = __floats2half2_rn(f0.z, f0.w);
    h[2] = __floats2half2_rn(f1.x, f1.y);
    h[3] = __floats2half2_rn(f1.z, f1.w);
    *reinterpret_cast<uint4*>(g_Xh + (size_t)m * HID + hv * 8) = *reinterpret_cast<uint4*>(h);
}

__global__ void w_to_half(const float* __restrict__ W) {
    int tid = blockIdx.x * blockDim.x + threadIdx.x;
    const float4* src = reinterpret_cast<const float4*>(W) + (size_t)tid * 2;
    float4 f0 = src[0], f1 = src[1];
    __half2 h[4];
    h[0] = __floats2half2_rn(f0.x, f0.y);
    h[1] = __floats2half2_rn(f0.z, f0.w);
    h[2] = __floats2half2_rn(f1.x, f1.y);
    h[3] = __floats2half2_rn(f1.z, f1.w);
    *reinterpret_cast<uint4*>(g_Wh + (size_t)tid * 8) = *reinterpret_cast<uint4*>(h);
}

__global__ void zero_flags() {
    int i = blockIdx.x * blockDim.x + threadIdx.x;
    if (i < NBLK) g_flag[i] = 0;
}

// ---------------------------------------------------------------------------
__device__ __forceinline__ void load_stage(const __half* __restrict__ Ag,
                                           const __half* __restrict__ Bg,
                                           uint32_t sstage, int tid, int k0h) {
#pragma unroll
    for (int i = 0; i < 4; i++) {
        int c = tid + 256 * i;
        int r = c >> 3, c8 = c & 7;
        cp16(sstage + r * 128 + ((c8 * 16) ^ ((r & 7) << 4)),
             Ag + (size_t)r * KTOT + k0h + c8 * 8);
    }
#pragma unroll
    for (int i = 0; i < 4; i++) {
        int c = tid + 256 * i;
        int r = c >> 3, c8 = c & 7;
        cp16(sstage + A_BYTES + r * 128 + ((c8 * 16) ^ ((r & 7) << 4)),
             Bg + (size_t)r * KTOT + k0h + c8 * 8);
    }
}

// fp16 GEMM: g_Yh[m,n] = sum_k g_Xh[m,k] * g_Wh[n,k]   (fp32 accumulate)
__global__ void __launch_bounds__(256, 2) qrnn_gemm_h(int dummy) {
    extern __shared__ float sm[];
    uint32_t sb = (uint32_t)__cvta_generic_to_shared(sm);
    const int tid = threadIdx.x;
    const int lane = tid & 31;
    const int warp = tid >> 5;
    const int wm = warp & 1;
    const int wn = warp >> 1;

    const int bid = blockIdx.x;
    const int grp = bid / 384;
    const int w_  = bid % 384;
    const int bm  = grp * 16 + (w_ & 15);
    const int bn  = w_ >> 4;

    const __half* Ag = g_Xh + (size_t)bm * BM * KTOT;
    const __half* Bg = g_Wh + (size_t)bn * BN * KTOT;

    const uint32_t xorp = (uint32_t)((lane & 7) << 4);
    const uint32_t aRowOff = (uint32_t)((wm * 64 + (lane & 7) + ((lane >> 3) & 1) * 8) * 128);
    const uint32_t bRowOff = (uint32_t)((wn * 32 + (lane & 7) + ((lane >> 4) & 1) * 8) * 128);
    const uint32_t akb = (uint32_t)((lane >> 4) * 16);
    const uint32_t bkb = (uint32_t)(((lane >> 3) & 1) * 16);

    float acc[4][4][4];
#pragma unroll
    for (int i = 0; i < 4; i++)
#pragma unroll
        for (int j = 0; j < 4; j++)
#pragma unroll
            for (int r = 0; r < 4; r++) acc[i][j][r] = 0.f;

#pragma unroll
    for (int s = 0; s < STAGES; s++) {
        load_stage(Ag, Bg, sb + s * STG_BYTES, tid, s * BKH);
        cp_commit();
    }

    for (int kt = 0; kt < KTILES; kt++) {
        asm volatile("cp.async.wait_group 2;\n" ::: "memory");
        __syncthreads();

        const uint32_t sA = sb + (uint32_t)(kt % STAGES) * STG_BYTES;
        const uint32_t sB = sA + A_BYTES;

#pragma unroll
        for (int ks = 0; ks < 4; ks++) {
            const uint32_t aK = (uint32_t)(ks * 32 + akb) ^ xorp;
            const uint32_t bK = (uint32_t)(ks * 32 + bkb) ^ xorp;
            uint32_t af[4][4], bf[2][4];
#pragma unroll
            for (int mt = 0; mt < 4; mt++)
                ldsm4(af[mt], sA + aRowOff + mt * 2048 + aK);
#pragma unroll
            for (int np = 0; np < 2; np++)
                ldsm4(bf[np], sB + bRowOff + np * 2048 + bK);
#pragma unroll
            for (int mt = 0; mt < 4; mt++)
#pragma unroll
                for (int nt = 0; nt < 4; nt++)
                    mma_f16(acc[mt][nt], af[mt], &bf[nt >> 1][(nt & 1) * 2]);
        }
        __syncthreads();

        int kn = kt + STAGES;
        if (kn < KTILES)
            load_stage(Ag, Bg, sb + (uint32_t)(kn % STAGES) * STG_BYTES, tid, kn * BKH);
        cp_commit();
    }

    const int g = lane >> 2, t = lane & 3;
#pragma unroll
    for (int mt = 0; mt < 4; mt++) {
        int r = bm * 128 + wm * 64 + mt * 16 + g;
#pragma unroll
        for (int nt = 0; nt < 4; nt++) {
            int c = bn * 128 + wn * 32 + nt * 8 + 2 * t;
            __half2* p0 = reinterpret_cast<__half2*>(g_Yh + (size_t)r * NTOT + c);
            __half2* p1 = reinterpret_cast<__half2*>(g_Yh + (size_t)(r + 8) * NTOT + c);
            *p0 = __floats2half2_rn(acc[mt][nt][0], acc[mt][nt][1]);
            *p1 = __floats2half2_rn(acc[mt][nt][2], acc[mt][nt][3]);
        }
    }
}

// ---------------------------------------------------------------------------
// Fused single-pass scan: gates once -> smem, chunk aggregate publish,
// decoupled look-back for the carry, replay from smem, write output.
// Block = (chunk, 256-channel group). blockIdx chunk-major => predecessors
// (same group, lower chunk) always have lower blockIdx.
__global__ void __launch_bounds__(256) qrnn_scan_fused(const float* __restrict__ bias,
                                                       float* __restrict__ outp, int slimit) {
    extern __shared__ float smem[];
    float* s_a  = smem;
    float* s_bb = smem + CS * 256;
    float* s_o  = smem + 2 * CS * 256;

    const int tid = threadIdx.x;
    const int bid = blockIdx.x;
    const int chunk = bid >> 6;
    const int grp   = bid & 63;
    const int ch = grp * 256 + tid;
    const int h = ch & (HID - 1);
    const int b = ch >> 10;

    const float bz  = bias[h];
    const float bfv = bias[HID + h];
    const float bo  = bias[2 * HID + h];

    const __half* __restrict__ Y = g_Yh;
    const int s0 = chunk * CS;
    size_t base = ((size_t)s0 * BATCH + b) * NTOT + h;

    float A = 1.f, B = 0.f;
#pragma unroll
    for (int i = 0; i < CS; ++i) {
        float zv = __half2float(Y[base])           + bz;
        float fv = __half2float(Y[base + HID])     + bfv;
        float ov = __half2float(Y[base + 2 * HID]) + bo;
        float f = sigmoidf_(fv);
        float z = tanhf_(zv);
        float o = sigmoidf_(ov);
        float a = 1.f - f;
        float bb = f * z;
        s_a [i * 256 + tid] = a;
        s_bb[i * 256 + tid] = bb;
        s_o [i * 256 + tid] = o;
        A *= a;
        B = fmaf(a, B, bb);
        base += (size_t)BATCH * NTOT;
    }

    // publish aggregate (chunks > 0) so successors can make progress
    if (chunk > 0) {
        g_AB[(size_t)bid * 256 + tid] = make_float2(A, B);
        __threadfence();
        __syncthreads();
        if (tid == 0) atomicExch(&g_flag[bid], 1);
    }

    // look-back: accumulate carry c_in (value of c entering this chunk)
    float c_in = 0.f;
    if (chunk > 0) {
        float accA = 1.f, accB = 0.f;
        int p = chunk - 1;
        while (true) {
            int pbid = p * 64 + grp;
            int fl;
            do {
                fl = *((volatile int*)(g_flag + pbid));
                if (!fl) __nanosleep(40);
            } while (!fl);
            __threadfence();
            if (fl == 2) {
                float v = g_incl[(size_t)pbid * 256 + tid];
                c_in = fmaf(accA, v, accB);
                break;
            } else {
                float2 ab = g_AB[(size_t)pbid * 256 + tid];
                accB = fmaf(accA, ab.y, accB);
                accA *= ab.x;
                if (--p < 0) { c_in = accB; break; }
            }
        }
    }

    // publish inclusive value for this chunk
    g_incl[(size_t)bid * 256 + tid] = fmaf(A, c_in, B);
    __threadfence();
    __syncthreads();
    if (tid == 0) atomicExch(&g_flag[bid], 2);

    // replay from smem (pure fma) and write output
    float c = c_in;
    if (outp) {
#pragma unroll
        for (int i = 0; i < CS; ++i) {
            c = fmaf(s_a[i * 256 + tid], c, s_bb[i * 256 + tid]);
            int s = s0 + i;
            if (s < slimit)
                outp[(size_t)s * NCH + ch] = s_o[i * 256 + tid] * c;
        }
    } else {
#pragma unroll
        for (int i = 0; i < CS; ++i) {
            c = fmaf(s_a[i * 256 + tid], c, s_bb[i * 256 + tid]);
            g_Xh[(size_t)(s0 + i) * NCH + ch] = __float2half(s_o[i * 256 + tid] * c);
        }
    }
}

// ---------------------------------------------------------------------------
extern "C" void kernel_launch(void* const* d_in, const int* in_sizes, int n_in,
                              void* d_out, int out_size) {
    const int*   x   = (const int*)d_in[0];
    const float* emb = (const float*)d_in[1];
    const float* W[3]  = {(const float*)d_in[2], (const float*)d_in[4], (const float*)d_in[6]};
    const float* bs[3] = {(const float*)d_in[3], (const float*)d_in[5], (const float*)d_in[7]};
    float* out = (float*)d_out;

    cudaFuncSetAttribute(qrnn_gemm_h, cudaFuncAttributeMaxDynamicSharedMemorySize, SMEM_BYTES);
    cudaFuncSetAttribute(qrnn_scan_fused, cudaFuncAttributeMaxDynamicSharedMemorySize, SCAN_SMEM);

    qrnn_embed<<<(MTOT * 128) / 256, 256>>>(x, emb);

    for (int l = 0; l < 3; l++) {
        w_to_half<<<(NTOT * KTOT / 8) / 256, 256>>>(W[l]);
        zero_flags<<<NBLK / 256, 256>>>();
        qrnn_gemm_h<<<(MTOT / BM) * (NTOT / BN), 256, SMEM_BYTES>>>(0);
        if (l < 2)
            qrnn_scan_fused<<<NBLK, 256, SCAN_SMEM>>>(bs[l], nullptr, S_LEN);
        else
            qrnn_scan_fused<<<NBLK, 256, SCAN_SMEM>>>(bs[l], out, S_LEN - 1);
    }
}